// round 7
// baseline (speedup 1.0000x reference)
#include <cuda_runtime.h>
#include <cuda_bf16.h>

// ---------------------------------------------------------------------------
// SpatialLiDAREncoder round 6: 8pts x 8outs register tile (balanced wf:fma).
//
//  - Per-thread tile 8 points x 8 outputs: per k per warp 4x LDS.128 (16 wf)
//    vs 32 FFMA2 -> per SM 128 wf : 128 fma cycles (was 192:128).
//  - 256 threads/block, 1 block/SM persistent, chunk = 128 points.
//  - Conflict-free weight layout: wA[k][og*4+r] r=0..3, wB[k][og*4+(r-4)].
//  - scatter: atomicMax on int bits (post-ReLU >= 0), output zeroed by memset.
// ---------------------------------------------------------------------------

#define NPT      120000
#define NALL     480000
#define HWSZ     16384
#define BSTRIDE  (128 * HWSZ)
#define CHUNK    128
#define NCHUNK   3750             // 480000 / 128
#define H1STR    132
#define H2STR    132
#define EPSF     1e-5f

typedef unsigned long long ull;

// Fused parameter storage (device globals -- no allocation).
__device__ float gW1f[256];        // [o][i] BN-scaled, o<64
__device__ float gB1f[64];
__device__ float gW2a[64 * 64];    // [k][og*4 + r],   r=0..3  (o = r*16+og)
__device__ float gW2b[64 * 64];    // [k][og*4 + r-4], r=4..7
__device__ float gB2s[128];        // [og*8 + r]
__device__ float gW3a[128 * 64];
__device__ float gW3b[128 * 64];
__device__ float gB3s[128];

// ---------------------------------------------------------------------------
__global__ void fuse_kernel(
    const float* __restrict__ W1, const float* __restrict__ b1,
    const float* __restrict__ g1, const float* __restrict__ be1,
    const float* __restrict__ m1, const float* __restrict__ v1,
    const float* __restrict__ W2, const float* __restrict__ b2,
    const float* __restrict__ g2, const float* __restrict__ be2,
    const float* __restrict__ m2, const float* __restrict__ v2,
    const float* __restrict__ W3, const float* __restrict__ b3,
    const float* __restrict__ g3, const float* __restrict__ be3,
    const float* __restrict__ m3, const float* __restrict__ v3)
{
    int tid = blockIdx.x * blockDim.x + threadIdx.x;
    int nt  = gridDim.x * blockDim.x;

    for (int i = tid; i < 256; i += nt) {
        int o = i >> 2;
        gW1f[i] = W1[i] * (g1[o] * rsqrtf(v1[o] + EPSF));
    }
    for (int o = tid; o < 64; o += nt) {
        float s = g1[o] * rsqrtf(v1[o] + EPSF);
        gB1f[o] = (b1[o] - m1[o]) * s + be1[o];
    }
    for (int i = tid; i < 128 * 64; i += nt) {
        int o = i >> 6, k = i & 63;
        float s = g2[o] * rsqrtf(v2[o] + EPSF);
        int r = o >> 4, og = o & 15;
        float v = W2[i] * s;
        if (r < 4) gW2a[k * 64 + og * 4 + r]     = v;
        else       gW2b[k * 64 + og * 4 + r - 4] = v;
    }
    for (int i = tid; i < 128 * 128; i += nt) {
        int o = i >> 7, k = i & 127;
        float s = g3[o] * rsqrtf(v3[o] + EPSF);
        int r = o >> 4, og = o & 15;
        float v = W3[i] * s;
        if (r < 4) gW3a[k * 64 + og * 4 + r]     = v;
        else       gW3b[k * 64 + og * 4 + r - 4] = v;
    }
    for (int o = tid; o < 128; o += nt) {
        int r = o >> 4, og = o & 15;
        float s2 = g2[o] * rsqrtf(v2[o] + EPSF);
        gB2s[og * 8 + r] = (b2[o] - m2[o]) * s2 + be2[o];
        float s3 = g3[o] * rsqrtf(v3[o] + EPSF);
        gB3s[og * 8 + r] = (b3[o] - m3[o]) * s3 + be3[o];
    }
}

// ---------------------------------------------------------------------------
__device__ __forceinline__ ull pk2(float x, float y) {
    ull r; asm("mov.b64 %0, {%1, %2};" : "=l"(r) : "f"(x), "f"(y)); return r;
}
__device__ __forceinline__ float2 up2(ull v) {
    float2 f; asm("mov.b64 {%0, %1}, %2;" : "=f"(f.x), "=f"(f.y) : "l"(v));
    return f;
}
__device__ __forceinline__ void fma2(ull& a, ull x, ull y) {
    asm("fma.rn.f32x2 %0, %1, %2, %0;" : "+l"(a) : "l"(x), "l"(y));
}

// Shared memory layout (float offsets)
#define SM_W2A 0
#define SM_W2B 4096
#define SM_W3A 8192
#define SM_W3B 16384
#define SM_W1  24576
#define SM_B1  24832
#define SM_B2  24896
#define SM_B3  25024
#define SM_H1  25152
#define SM_H2  (SM_H1 + 64 * H1STR)    // 33600
#define SM_PT  (SM_H2 + 128 * H2STR)   // 50496
#define SM_CL  (SM_PT + 512)           // 51008
#define SM_TOT (SM_CL + 128)           // 51136
#define SMEM_BYTES (SM_TOT * 4)        // 204544

__global__ void __launch_bounds__(256, 1)
mlp_scatter_kernel(const float4* __restrict__ ptsg, float* __restrict__ out)
{
    extern __shared__ float sm[];
    float* w2a = sm + SM_W2A;
    float* w2b = sm + SM_W2B;
    float* w3a = sm + SM_W3A;
    float* w3b = sm + SM_W3B;
    float* w1s = sm + SM_W1;
    float* b1s = sm + SM_B1;
    float* b2s = sm + SM_B2;
    float* b3s = sm + SM_B3;
    float* h1  = sm + SM_H1;
    float* h2  = sm + SM_H2;
    float4* ptsS  = (float4*)(sm + SM_PT);
    int*    cellS = (int*)(sm + SM_CL);

    const int t = threadIdx.x;

    // Stage fused weights (block is persistent; done once).
    for (int i = t; i < 4096; i += 256) { w2a[i] = gW2a[i]; w2b[i] = gW2b[i]; }
    for (int i = t; i < 8192; i += 256) { w3a[i] = gW3a[i]; w3b[i] = gW3b[i]; }
    if (t < 256) w1s[t] = gW1f[t];
    if (t < 64)  b1s[t] = gB1f[t];
    if (t < 128) { b2s[t] = gB2s[t]; b3s[t] = gB3s[t]; }
    __syncthreads();

    const int og = t & 15;        // output group: o = r*16 + og, r = 0..7
    const int pg = t >> 4;        // point group: points pg*8 .. pg*8+7
    ull bias2[4], bias3[4];
#pragma unroll
    for (int j = 0; j < 4; ++j) {
        bias2[j] = *(const ull*)(b2s + og * 8 + 2 * j);
        bias3[j] = *(const ull*)(b3s + og * 8 + 2 * j);
    }
    const int p1  = t & 127;          // layer1: this thread's point
    const int ob1 = (t >> 7) * 32;    // layer1: output base (32 outputs)

    const float* w2ap = w2a + og * 4;
    const float* w2bp = w2b + og * 4;
    const float* w3ap = w3a + og * 4;
    const float* w3bp = w3b + og * 4;
    const float* h1p  = h1 + pg * 8;
    const float* h2p  = h2 + pg * 8;

    for (int c = blockIdx.x; c < NCHUNK; c += gridDim.x) {
        const int gp = c * CHUNK;

        // -- stage points + cell offsets ------------------------------------
        if (t < CHUNK) {
            float4 p = ptsg[gp + t];
            ptsS[t] = p;
            float xn = (p.x + 50.f) * 0.01f;
            float yn = (p.y + 50.f) * 0.01f;
            bool valid = (xn >= 0.f) && (xn <= 1.f) && (yn >= 0.f) && (yn <= 1.f);
            int gx = min(max((int)(xn * 127.f), 0), 127);
            int gy = min(max((int)(yn * 127.f), 0), 127);
            int b  = (gp + t) / NPT;
            cellS[t] = valid ? b * BSTRIDE + gy * 128 + gx : -1;
        }
        __syncthreads();

        // -- layer 1: 4 -> 64 (each thread: 1 point, 32 outputs) -------------
        {
            float4 pv = ptsS[p1];
#pragma unroll 8
            for (int r = 0; r < 32; ++r) {
                int o = ob1 + r;
                float4 w = *(const float4*)(w1s + o * 4);
                float s = b1s[o] + pv.x * w.x + pv.y * w.y
                                 + pv.z * w.z + pv.w * w.w;
                h1[o * H1STR + p1] = fmaxf(s, 0.f);
            }
        }
        __syncthreads();

        // -- layer 2: 64 -> 128 (tile 8p x 8o) ------------------------------
        ull acc[32];
#pragma unroll
        for (int p = 0; p < 8; ++p)
#pragma unroll
            for (int j = 0; j < 4; ++j) acc[p * 4 + j] = bias2[j];

#pragma unroll 4
        for (int k = 0; k < 64; ++k) {
            ulonglong2 wa = *(const ulonglong2*)(w2ap + k * 64);
            ulonglong2 wb = *(const ulonglong2*)(w2bp + k * 64);
            float4 ha = *(const float4*)(h1p + k * H1STR);
            float4 hb = *(const float4*)(h1p + k * H1STR + 4);
            ull hp[8];
            hp[0] = pk2(ha.x, ha.x); hp[1] = pk2(ha.y, ha.y);
            hp[2] = pk2(ha.z, ha.z); hp[3] = pk2(ha.w, ha.w);
            hp[4] = pk2(hb.x, hb.x); hp[5] = pk2(hb.y, hb.y);
            hp[6] = pk2(hb.z, hb.z); hp[7] = pk2(hb.w, hb.w);
#pragma unroll
            for (int p = 0; p < 8; ++p) {
                fma2(acc[p * 4 + 0], hp[p], wa.x);
                fma2(acc[p * 4 + 1], hp[p], wa.y);
                fma2(acc[p * 4 + 2], hp[p], wb.x);
                fma2(acc[p * 4 + 3], hp[p], wb.y);
            }
        }
        // epilogue: ReLU + store h2 rows [o = r*16+og]
        {
            float vals[8][8];
#pragma unroll
            for (int p = 0; p < 8; ++p)
#pragma unroll
                for (int j = 0; j < 4; ++j) {
                    float2 v = up2(acc[p * 4 + j]);
                    vals[p][2 * j]     = fmaxf(v.x, 0.f);
                    vals[p][2 * j + 1] = fmaxf(v.y, 0.f);
                }
#pragma unroll
            for (int r = 0; r < 8; ++r) {
                float* dst = h2 + (r * 16 + og) * H2STR + pg * 8;
                *(float4*)(dst)     = make_float4(vals[0][r], vals[1][r],
                                                  vals[2][r], vals[3][r]);
                *(float4*)(dst + 4) = make_float4(vals[4][r], vals[5][r],
                                                  vals[6][r], vals[7][r]);
            }
        }
        __syncthreads();

        // -- layer 3: 128 -> 128 + scatter-max ------------------------------
#pragma unroll
        for (int p = 0; p < 8; ++p)
#pragma unroll
            for (int j = 0; j < 4; ++j) acc[p * 4 + j] = bias3[j];

#pragma unroll 4
        for (int k = 0; k < 128; ++k) {
            ulonglong2 wa = *(const ulonglong2*)(w3ap + k * 64);
            ulonglong2 wb = *(const ulonglong2*)(w3bp + k * 64);
            float4 ha = *(const float4*)(h2p + k * H2STR);
            float4 hb = *(const float4*)(h2p + k * H2STR + 4);
            ull hp[8];
            hp[0] = pk2(ha.x, ha.x); hp[1] = pk2(ha.y, ha.y);
            hp[2] = pk2(ha.z, ha.z); hp[3] = pk2(ha.w, ha.w);
            hp[4] = pk2(hb.x, hb.x); hp[5] = pk2(hb.y, hb.y);
            hp[6] = pk2(hb.z, hb.z); hp[7] = pk2(hb.w, hb.w);
#pragma unroll
            for (int p = 0; p < 8; ++p) {
                fma2(acc[p * 4 + 0], hp[p], wa.x);
                fma2(acc[p * 4 + 1], hp[p], wa.y);
                fma2(acc[p * 4 + 2], hp[p], wb.x);
                fma2(acc[p * 4 + 3], hp[p], wb.y);
            }
        }
        {
            int cells[8];
#pragma unroll
            for (int p = 0; p < 8; ++p) cells[p] = cellS[pg * 8 + p];
#pragma unroll
            for (int p = 0; p < 8; ++p) {
                if (cells[p] < 0) continue;
                float* ob = out + cells[p];
#pragma unroll
                for (int j = 0; j < 4; ++j) {
                    float2 v = up2(acc[p * 4 + j]);
                    atomicMax((int*)(ob + ((2 * j) * 16 + og) * HWSZ),
                              __float_as_int(fmaxf(v.x, 0.f)));
                    atomicMax((int*)(ob + ((2 * j + 1) * 16 + og) * HWSZ),
                              __float_as_int(fmaxf(v.y, 0.f)));
                }
            }
        }
        __syncthreads();   // protect pts/cell/h1/h2 before next chunk
    }
}

// ---------------------------------------------------------------------------
extern "C" void kernel_launch(void* const* d_in, const int* in_sizes, int n_in,
                              void* d_out, int out_size)
{
    (void)in_sizes; (void)n_in;
    const float* points = (const float*)d_in[0];

    cudaMemsetAsync(d_out, 0, (size_t)out_size * sizeof(float), 0);

    fuse_kernel<<<32, 256>>>(
        (const float*)d_in[1],  (const float*)d_in[2],  (const float*)d_in[3],
        (const float*)d_in[4],  (const float*)d_in[5],  (const float*)d_in[6],
        (const float*)d_in[7],  (const float*)d_in[8],  (const float*)d_in[9],
        (const float*)d_in[10], (const float*)d_in[11], (const float*)d_in[12],
        (const float*)d_in[13], (const float*)d_in[14], (const float*)d_in[15],
        (const float*)d_in[16], (const float*)d_in[17], (const float*)d_in[18]);

    int dev = 0;
    cudaGetDevice(&dev);
    int nsm = 0;
    cudaDeviceGetAttribute(&nsm, cudaDevAttrMultiProcessorCount, dev);
    if (nsm <= 0) nsm = 148;

    cudaFuncSetAttribute(mlp_scatter_kernel,
                         cudaFuncAttributeMaxDynamicSharedMemorySize,
                         SMEM_BYTES);
    mlp_scatter_kernel<<<nsm, 256, SMEM_BYTES>>>((const float4*)points,
                                                 (float*)d_out);
}

// round 9
// speedup vs baseline: 1.0213x; 1.0213x over previous
#include <cuda_runtime.h>
#include <cuda_bf16.h>

// ---------------------------------------------------------------------------
// SpatialLiDAREncoder round 8: 8p x 8o balanced tile at 12 warps/SM.
//
//  - 384 threads/block, 1 block/SM persistent, chunk = 192 points
//    (16 og-groups x 24 point-groups).
//  - h2 staged in a HALF buffer (64 rows): layer2 wA outs are exactly h2 rows
//    0-63, wB outs rows 64-127. Sequence: L2A->h2buf, L2B->regs, sync,
//    L3 partial k=0..63, sync, h2buf <- L2B, sync, L3 k=64..127, scatter.
//  - Conflict-free weight layout: wA[k][og*4+r] r=0..3, wB[k][og*4+(r-4)].
//  - scatter: atomicMax on int bits (post-ReLU >= 0), output zeroed by memset.
// ---------------------------------------------------------------------------

#define NPT      120000
#define NALL     480000
#define HWSZ     16384
#define BSTRIDE  (128 * HWSZ)
#define CHUNK    192
#define NCHUNK   2500             // 480000 / 192 (120000/192=625: no batch span)
#define H1STR    200              // 192 + 8 pad
#define H2STR    200
#define EPSF     1e-5f

typedef unsigned long long ull;

// Fused parameter storage (device globals -- no allocation).
__device__ float gW1f[256];        // [o][i] BN-scaled, o<64
__device__ float gB1f[64];
__device__ float gW2a[64 * 64];    // [k][og*4 + r],   r=0..3  (o = r*16+og)
__device__ float gW2b[64 * 64];    // [k][og*4 + r-4], r=4..7
__device__ float gB2s[128];        // [og*8 + r]
__device__ float gW3a[128 * 64];
__device__ float gW3b[128 * 64];
__device__ float gB3s[128];

// ---------------------------------------------------------------------------
__global__ void fuse_kernel(
    const float* __restrict__ W1, const float* __restrict__ b1,
    const float* __restrict__ g1, const float* __restrict__ be1,
    const float* __restrict__ m1, const float* __restrict__ v1,
    const float* __restrict__ W2, const float* __restrict__ b2,
    const float* __restrict__ g2, const float* __restrict__ be2,
    const float* __restrict__ m2, const float* __restrict__ v2,
    const float* __restrict__ W3, const float* __restrict__ b3,
    const float* __restrict__ g3, const float* __restrict__ be3,
    const float* __restrict__ m3, const float* __restrict__ v3)
{
    int tid = blockIdx.x * blockDim.x + threadIdx.x;
    int nt  = gridDim.x * blockDim.x;

    for (int i = tid; i < 256; i += nt) {
        int o = i >> 2;
        gW1f[i] = W1[i] * (g1[o] * rsqrtf(v1[o] + EPSF));
    }
    for (int o = tid; o < 64; o += nt) {
        float s = g1[o] * rsqrtf(v1[o] + EPSF);
        gB1f[o] = (b1[o] - m1[o]) * s + be1[o];
    }
    for (int i = tid; i < 128 * 64; i += nt) {
        int o = i >> 6, k = i & 63;
        float s = g2[o] * rsqrtf(v2[o] + EPSF);
        int r = o >> 4, og = o & 15;
        float v = W2[i] * s;
        if (r < 4) gW2a[k * 64 + og * 4 + r]     = v;
        else       gW2b[k * 64 + og * 4 + r - 4] = v;
    }
    for (int i = tid; i < 128 * 128; i += nt) {
        int o = i >> 7, k = i & 127;
        float s = g3[o] * rsqrtf(v3[o] + EPSF);
        int r = o >> 4, og = o & 15;
        float v = W3[i] * s;
        if (r < 4) gW3a[k * 64 + og * 4 + r]     = v;
        else       gW3b[k * 64 + og * 4 + r - 4] = v;
    }
    for (int o = tid; o < 128; o += nt) {
        int r = o >> 4, og = o & 15;
        float s2 = g2[o] * rsqrtf(v2[o] + EPSF);
        gB2s[og * 8 + r] = (b2[o] - m2[o]) * s2 + be2[o];
        float s3 = g3[o] * rsqrtf(v3[o] + EPSF);
        gB3s[og * 8 + r] = (b3[o] - m3[o]) * s3 + be3[o];
    }
}

// ---------------------------------------------------------------------------
__device__ __forceinline__ ull pk2(float x, float y) {
    ull r; asm("mov.b64 %0, {%1, %2};" : "=l"(r) : "f"(x), "f"(y)); return r;
}
__device__ __forceinline__ float2 up2(ull v) {
    float2 f; asm("mov.b64 {%0, %1}, %2;" : "=f"(f.x), "=f"(f.y) : "l"(v));
    return f;
}
__device__ __forceinline__ void fma2(ull& a, ull x, ull y) {
    asm("fma.rn.f32x2 %0, %1, %2, %0;" : "+l"(a) : "l"(x), "l"(y));
}

// Shared memory layout (float offsets)
#define SM_W2A 0
#define SM_W2B 4096
#define SM_W3A 8192
#define SM_W3B 16384
#define SM_W1  24576
#define SM_B1  24832
#define SM_B2  24896
#define SM_B3  25024
#define SM_H1  25152
#define SM_H2  (SM_H1 + 64 * H1STR)    // 37952  (h2 HALF buffer: 64 rows)
#define SM_PT  (SM_H2 + 64 * H2STR)    // 50752
#define SM_CL  (SM_PT + 768)           // 51520
#define SM_TOT (SM_CL + 192)           // 51712
#define SMEM_BYTES (SM_TOT * 4)        // 206848

// 16 FFMA2 block: 8 points x 2 output-pairs from one weight ulonglong2.
__device__ __forceinline__ void tile8x4(ull* __restrict__ acc /*16*/,
                                        const ull* __restrict__ hp /*8*/,
                                        ulonglong2 w)
{
#pragma unroll
    for (int p = 0; p < 8; ++p) {
        fma2(acc[p * 2 + 0], hp[p], w.x);
        fma2(acc[p * 2 + 1], hp[p], w.y);
    }
}

__device__ __forceinline__ void packrow(ull* __restrict__ hp,
                                        const float* __restrict__ src)
{
    float4 ha = *(const float4*)(src);
    float4 hb = *(const float4*)(src + 4);
    hp[0] = pk2(ha.x, ha.x); hp[1] = pk2(ha.y, ha.y);
    hp[2] = pk2(ha.z, ha.z); hp[3] = pk2(ha.w, ha.w);
    hp[4] = pk2(hb.x, hb.x); hp[5] = pk2(hb.y, hb.y);
    hp[6] = pk2(hb.z, hb.z); hp[7] = pk2(hb.w, hb.w);
}

// ReLU 16 accs (8p x 2 pairs = 8p x 4 outs) and store as 4 rows x float4x2.
__device__ __forceinline__ void store4rows(const ull* __restrict__ acc,
                                           float* __restrict__ h2,
                                           int og, int pg)
{
    float vals[8][4];
#pragma unroll
    for (int p = 0; p < 8; ++p)
#pragma unroll
        for (int j = 0; j < 2; ++j) {
            float2 v = up2(acc[p * 2 + j]);
            vals[p][2 * j]     = fmaxf(v.x, 0.f);
            vals[p][2 * j + 1] = fmaxf(v.y, 0.f);
        }
#pragma unroll
    for (int r = 0; r < 4; ++r) {
        float* dst = h2 + (r * 16 + og) * H2STR + pg * 8;
        *(float4*)(dst)     = make_float4(vals[0][r], vals[1][r],
                                          vals[2][r], vals[3][r]);
        *(float4*)(dst + 4) = make_float4(vals[4][r], vals[5][r],
                                          vals[6][r], vals[7][r]);
    }
}

__global__ void __launch_bounds__(384, 1)
mlp_scatter_kernel(const float4* __restrict__ ptsg, float* __restrict__ out)
{
    extern __shared__ float sm[];
    float* w2a = sm + SM_W2A;
    float* w2b = sm + SM_W2B;
    float* w3a = sm + SM_W3A;
    float* w3b = sm + SM_W3B;
    float* w1s = sm + SM_W1;
    float* b1s = sm + SM_B1;
    float* b2s = sm + SM_B2;
    float* b3s = sm + SM_B3;
    float* h1  = sm + SM_H1;
    float* h2  = sm + SM_H2;       // 64-row half buffer
    float4* ptsS  = (float4*)(sm + SM_PT);
    int*    cellS = (int*)(sm + SM_CL);

    const int t = threadIdx.x;

    // Stage fused weights (block is persistent; done once).
    for (int i = t; i < 4096; i += 384) { w2a[i] = gW2a[i]; w2b[i] = gW2b[i]; }
    for (int i = t; i < 8192; i += 384) { w3a[i] = gW3a[i]; w3b[i] = gW3b[i]; }
    if (t < 256) w1s[t] = gW1f[t];
    if (t < 64)  b1s[t] = gB1f[t];
    if (t < 128) { b2s[t] = gB2s[t]; b3s[t] = gB3s[t]; }
    __syncthreads();

    const int og = t & 15;        // output group: o = r*16 + og
    const int pg = t >> 4;        // point group: points pg*8 .. pg*8+7 (pg<24)
    ull bias2[4], bias3[4];
#pragma unroll
    for (int j = 0; j < 4; ++j) {
        bias2[j] = *(const ull*)(b2s + og * 8 + 2 * j);
        bias3[j] = *(const ull*)(b3s + og * 8 + 2 * j);
    }
    const int g1i = t / 192;           // layer1 half
    const int p1  = t - g1i * 192;     // layer1: this thread's point
    const int ob1 = g1i * 32;          // layer1: output base (32 outputs)

    const float* w2ap = w2a + og * 4;
    const float* w2bp = w2b + og * 4;
    const float* w3ap = w3a + og * 4;
    const float* w3bp = w3b + og * 4;
    const float* h1p  = h1 + pg * 8;
    const float* h2p  = h2 + pg * 8;

    for (int c = blockIdx.x; c < NCHUNK; c += gridDim.x) {
        const int gp = c * CHUNK;

        // -- stage points + cell offsets ------------------------------------
        if (t < CHUNK) {
            float4 p = ptsg[gp + t];
            ptsS[t] = p;
            float xn = (p.x + 50.f) * 0.01f;
            float yn = (p.y + 50.f) * 0.01f;
            bool valid = (xn >= 0.f) && (xn <= 1.f) && (yn >= 0.f) && (yn <= 1.f);
            int gx = min(max((int)(xn * 127.f), 0), 127);
            int gy = min(max((int)(yn * 127.f), 0), 127);
            int b  = (gp + t) / NPT;
            cellS[t] = valid ? b * BSTRIDE + gy * 128 + gx : -1;
        }
        __syncthreads();

        // -- layer 1: 4 -> 64 (each thread: 1 point, 32 outputs) -------------
        {
            float4 pv = ptsS[p1];
#pragma unroll 8
            for (int r = 0; r < 32; ++r) {
                int o = ob1 + r;
                float4 w = *(const float4*)(w1s + o * 4);
                float s = b1s[o] + pv.x * w.x + pv.y * w.y
                                 + pv.z * w.z + pv.w * w.w;
                h1[o * H1STR + p1] = fmaxf(s, 0.f);
            }
        }
        __syncthreads();

        // -- layer 2A: outs r=0..3 (h2 rows 0-63) -> h2buf ------------------
        ull acc2[16];
#pragma unroll
        for (int p = 0; p < 8; ++p) {
            acc2[p * 2 + 0] = bias2[0];
            acc2[p * 2 + 1] = bias2[1];
        }
#pragma unroll 4
        for (int k = 0; k < 64; ++k) {
            ulonglong2 wa = *(const ulonglong2*)(w2ap + k * 64);
            ull hp[8];
            packrow(hp, h1p + k * H1STR);
            tile8x4(acc2, hp, wa);
        }
        store4rows(acc2, h2, og, pg);

        // -- layer 2B: outs r=4..7 (h2 rows 64-127) -> registers ------------
        ull acc2b[16];
#pragma unroll
        for (int p = 0; p < 8; ++p) {
            acc2b[p * 2 + 0] = bias2[2];
            acc2b[p * 2 + 1] = bias2[3];
        }
#pragma unroll 4
        for (int k = 0; k < 64; ++k) {
            ulonglong2 wb = *(const ulonglong2*)(w2bp + k * 64);
            ull hp[8];
            packrow(hp, h1p + k * H1STR);
            tile8x4(acc2b, hp, wb);
        }
        __syncthreads();   // h2 rows 0-63 visible

        // -- layer 3 first half: k = 0..63 ----------------------------------
        ull acc3[32];
#pragma unroll
        for (int p = 0; p < 8; ++p)
#pragma unroll
            for (int j = 0; j < 4; ++j) acc3[p * 4 + j] = bias3[j];

#pragma unroll 4
        for (int k = 0; k < 64; ++k) {
            ulonglong2 wa = *(const ulonglong2*)(w3ap + k * 64);
            ulonglong2 wb = *(const ulonglong2*)(w3bp + k * 64);
            ull hp[8];
            packrow(hp, h2p + k * H2STR);
#pragma unroll
            for (int p = 0; p < 8; ++p) {
                fma2(acc3[p * 4 + 0], hp[p], wa.x);
                fma2(acc3[p * 4 + 1], hp[p], wa.y);
                fma2(acc3[p * 4 + 2], hp[p], wb.x);
                fma2(acc3[p * 4 + 3], hp[p], wb.y);
            }
        }
        __syncthreads();   // all reads of h2 rows 0-63 done

        // -- publish layer 2B results (h2 rows 64-127 -> same buffer) -------
        store4rows(acc2b, h2, og, pg);
        __syncthreads();   // h2 rows 64-127 visible

        // -- layer 3 second half: k = 64..127 -------------------------------
#pragma unroll 4
        for (int k = 64; k < 128; ++k) {
            ulonglong2 wa = *(const ulonglong2*)(w3ap + k * 64);
            ulonglong2 wb = *(const ulonglong2*)(w3bp + k * 64);
            ull hp[8];
            packrow(hp, h2p + (k - 64) * H2STR);
#pragma unroll
            for (int p = 0; p < 8; ++p) {
                fma2(acc3[p * 4 + 0], hp[p], wa.x);
                fma2(acc3[p * 4 + 1], hp[p], wa.y);
                fma2(acc3[p * 4 + 2], hp[p], wb.x);
                fma2(acc3[p * 4 + 3], hp[p], wb.y);
            }
        }

        // -- scatter-max ----------------------------------------------------
        {
            int cells[8];
#pragma unroll
            for (int p = 0; p < 8; ++p) cells[p] = cellS[pg * 8 + p];
#pragma unroll
            for (int p = 0; p < 8; ++p) {
                if (cells[p] < 0) continue;
                float* ob = out + cells[p];
#pragma unroll
                for (int j = 0; j < 4; ++j) {
                    float2 v = up2(acc3[p * 4 + j]);
                    atomicMax((int*)(ob + ((2 * j) * 16 + og) * HWSZ),
                              __float_as_int(fmaxf(v.x, 0.f)));
                    atomicMax((int*)(ob + ((2 * j + 1) * 16 + og) * HWSZ),
                              __float_as_int(fmaxf(v.y, 0.f)));
                }
            }
        }
        __syncthreads();   // protect pts/cell/h1/h2 before next chunk
    }
}

// ---------------------------------------------------------------------------
extern "C" void kernel_launch(void* const* d_in, const int* in_sizes, int n_in,
                              void* d_out, int out_size)
{
    (void)in_sizes; (void)n_in;
    const float* points = (const float*)d_in[0];

    cudaMemsetAsync(d_out, 0, (size_t)out_size * sizeof(float), 0);

    fuse_kernel<<<32, 256>>>(
        (const float*)d_in[1],  (const float*)d_in[2],  (const float*)d_in[3],
        (const float*)d_in[4],  (const float*)d_in[5],  (const float*)d_in[6],
        (const float*)d_in[7],  (const float*)d_in[8],  (const float*)d_in[9],
        (const float*)d_in[10], (const float*)d_in[11], (const float*)d_in[12],
        (const float*)d_in[13], (const float*)d_in[14], (const float*)d_in[15],
        (const float*)d_in[16], (const float*)d_in[17], (const float*)d_in[18]);

    int dev = 0;
    cudaGetDevice(&dev);
    int nsm = 0;
    cudaDeviceGetAttribute(&nsm, cudaDevAttrMultiProcessorCount, dev);
    if (nsm <= 0) nsm = 148;

    cudaFuncSetAttribute(mlp_scatter_kernel,
                         cudaFuncAttributeMaxDynamicSharedMemorySize,
                         SMEM_BYTES);
    mlp_scatter_kernel<<<nsm, 384, SMEM_BYTES>>>((const float4*)points,
                                                 (float*)d_out);
}

// round 13
// speedup vs baseline: 1.1076x; 1.0845x over previous
#include <cuda_runtime.h>
#include <cuda_bf16.h>

// ---------------------------------------------------------------------------
// SpatialLiDAREncoder round 11: cell-sorted points + run-merged scatter.
//
//  - Pre-pass: counting sort of points by BEV cell (histogram -> scan ->
//    scatter). Invalid points (~18%) dropped entirely.
//  - Main kernel = round-5 MLP (512 thr, 4p x 8o f32x2 tile, conflict-free
//    weight layout), but: points gathered via sorted index, chunk count is
//    dynamic (n_valid), and the scatter merges consecutive same-cell points
//    in registers before issuing atomicMax (sorted -> runs are adjacent).
//  - scatter: atomicMax on int bits (post-ReLU >= 0), d_out zeroed by memset.
// ---------------------------------------------------------------------------

#define NPT      120000
#define NALL     480000
#define HWSZ     16384
#define BSTRIDE  (128 * HWSZ)
#define CHUNK    128
#define H1STR    132
#define H2STR    132
#define EPSF     1e-5f

typedef unsigned long long ull;

// Fused parameter storage (device globals -- no allocation).
__device__ float gW1f[256];        // [o][i] BN-scaled, o<64
__device__ float gB1f[64];
__device__ float gW2a[64 * 64];    // [k][og*4 + r],   r=0..3  (o = r*16+og)
__device__ float gW2b[64 * 64];    // [k][og*4 + r-4], r=4..7
__device__ float gB2s[128];        // [og*8 + r]
__device__ float gW3a[128 * 64];
__device__ float gW3b[128 * 64];
__device__ float gB3s[128];

// Sorting scratch (device globals -- no allocation).
__device__ int gHist[65536];       // per-cell histogram (zeroed each call)
__device__ int gOff[65536];        // exclusive offsets (then running ctrs)
__device__ int gNvalid;            // total valid points
__device__ int gCellArr[NALL];     // cell per original point (-1 invalid)
__device__ int gSortedIdx[NALL];   // original index, sorted by cell
__device__ int gSortedCell[NALL];  // cell id, sorted

// ---------------------------------------------------------------------------
__global__ void fuse_kernel(
    const float* __restrict__ W1, const float* __restrict__ b1,
    const float* __restrict__ g1, const float* __restrict__ be1,
    const float* __restrict__ m1, const float* __restrict__ v1,
    const float* __restrict__ W2, const float* __restrict__ b2,
    const float* __restrict__ g2, const float* __restrict__ be2,
    const float* __restrict__ m2, const float* __restrict__ v2,
    const float* __restrict__ W3, const float* __restrict__ b3,
    const float* __restrict__ g3, const float* __restrict__ be3,
    const float* __restrict__ m3, const float* __restrict__ v3)
{
    int tid = blockIdx.x * blockDim.x + threadIdx.x;
    int nt  = gridDim.x * blockDim.x;

    for (int i = tid; i < 256; i += nt) {
        int o = i >> 2;
        gW1f[i] = W1[i] * (g1[o] * rsqrtf(v1[o] + EPSF));
    }
    for (int o = tid; o < 64; o += nt) {
        float s = g1[o] * rsqrtf(v1[o] + EPSF);
        gB1f[o] = (b1[o] - m1[o]) * s + be1[o];
    }
    for (int i = tid; i < 128 * 64; i += nt) {
        int o = i >> 6, k = i & 63;
        float s = g2[o] * rsqrtf(v2[o] + EPSF);
        int r = o >> 4, og = o & 15;
        float v = W2[i] * s;
        if (r < 4) gW2a[k * 64 + og * 4 + r]     = v;
        else       gW2b[k * 64 + og * 4 + r - 4] = v;
    }
    for (int i = tid; i < 128 * 128; i += nt) {
        int o = i >> 7, k = i & 127;
        float s = g3[o] * rsqrtf(v3[o] + EPSF);
        int r = o >> 4, og = o & 15;
        float v = W3[i] * s;
        if (r < 4) gW3a[k * 64 + og * 4 + r]     = v;
        else       gW3b[k * 64 + og * 4 + r - 4] = v;
    }
    for (int o = tid; o < 128; o += nt) {
        int r = o >> 4, og = o & 15;
        float s2 = g2[o] * rsqrtf(v2[o] + EPSF);
        gB2s[og * 8 + r] = (b2[o] - m2[o]) * s2 + be2[o];
        float s3 = g3[o] * rsqrtf(v3[o] + EPSF);
        gB3s[og * 8 + r] = (b3[o] - m3[o]) * s3 + be3[o];
    }
}

// ---------------------------------------------------------------------------
// Sorting pre-pass.
__global__ void bin_kernel(const float4* __restrict__ pts)
{
    int i = blockIdx.x * blockDim.x + threadIdx.x;
    if (i >= NALL) return;
    float4 p = pts[i];
    float xn = (p.x + 50.f) * 0.01f;
    float yn = (p.y + 50.f) * 0.01f;
    bool valid = (xn >= 0.f) && (xn <= 1.f) && (yn >= 0.f) && (yn <= 1.f);
    int gx = min(max((int)(xn * 127.f), 0), 127);
    int gy = min(max((int)(yn * 127.f), 0), 127);
    int b  = i / NPT;
    int sc = valid ? (b * HWSZ + gy * 128 + gx) : -1;
    gCellArr[i] = sc;
    if (sc >= 0) atomicAdd(&gHist[sc], 1);
}

__global__ void scan_kernel()   // single block, 256 threads
{
    __shared__ int ssum[256];
    int t = threadIdx.x;
    int base = t * 256;
    int s = 0;
#pragma unroll 8
    for (int i = 0; i < 256; ++i) s += gHist[base + i];
    ssum[t] = s;
    __syncthreads();
    // Hillis-Steele inclusive scan over 256 partial sums
    for (int d = 1; d < 256; d <<= 1) {
        int v = (t >= d) ? ssum[t - d] : 0;
        __syncthreads();
        ssum[t] += v;
        __syncthreads();
    }
    int run = (t == 0) ? 0 : ssum[t - 1];
#pragma unroll 8
    for (int i = 0; i < 256; ++i) {
        int h = gHist[base + i];
        gOff[base + i] = run;
        run += h;
    }
    if (t == 255) gNvalid = run;
}

__global__ void sort_kernel()
{
    int i = blockIdx.x * blockDim.x + threadIdx.x;
    if (i >= NALL) return;
    int sc = gCellArr[i];
    if (sc >= 0) {
        int pos = atomicAdd(&gOff[sc], 1);
        gSortedIdx[pos]  = i;
        gSortedCell[pos] = sc;
    }
}

// ---------------------------------------------------------------------------
__device__ __forceinline__ ull pk2(float x, float y) {
    ull r; asm("mov.b64 %0, {%1, %2};" : "=l"(r) : "f"(x), "f"(y)); return r;
}
__device__ __forceinline__ float2 up2(ull v) {
    float2 f; asm("mov.b64 {%0, %1}, %2;" : "=f"(f.x), "=f"(f.y) : "l"(v));
    return f;
}
__device__ __forceinline__ void fma2(ull& a, ull x, ull y) {
    asm("fma.rn.f32x2 %0, %1, %2, %0;" : "+l"(a) : "l"(x), "l"(y));
}

// Shared memory layout (float offsets)
#define SM_W2A 0
#define SM_W2B 4096
#define SM_W3A 8192
#define SM_W3B 16384
#define SM_W1  24576
#define SM_B1  24832
#define SM_B2  24896
#define SM_B3  25024
#define SM_H1  25152
#define SM_H2  (SM_H1 + 64 * H1STR)    // 33600
#define SM_PT  (SM_H2 + 128 * H2STR)   // 50496
#define SM_CL  (SM_PT + 512)           // 51008
#define SM_TOT (SM_CL + 128)           // 51136
#define SMEM_BYTES (SM_TOT * 4)        // 204544

__global__ void __launch_bounds__(512, 1)
mlp_scatter_kernel(const float4* __restrict__ ptsg, float* __restrict__ out)
{
    extern __shared__ float sm[];
    float* w2a = sm + SM_W2A;
    float* w2b = sm + SM_W2B;
    float* w3a = sm + SM_W3A;
    float* w3b = sm + SM_W3B;
    float* w1s = sm + SM_W1;
    float* b1s = sm + SM_B1;
    float* b2s = sm + SM_B2;
    float* b3s = sm + SM_B3;
    float* h1  = sm + SM_H1;
    float* h2  = sm + SM_H2;
    float4* ptsS  = (float4*)(sm + SM_PT);
    int*    cellS = (int*)(sm + SM_CL);

    const int t = threadIdx.x;

    // Stage fused weights (block is persistent; done once).
    for (int i = t; i < 4096; i += 512) { w2a[i] = gW2a[i]; w2b[i] = gW2b[i]; }
    for (int i = t; i < 8192; i += 512) { w3a[i] = gW3a[i]; w3b[i] = gW3b[i]; }
    if (t < 256) w1s[t] = gW1f[t];
    if (t < 64)  b1s[t] = gB1f[t];
    if (t < 128) { b2s[t] = gB2s[t]; b3s[t] = gB3s[t]; }
    __syncthreads();

    const int og = t & 15;        // output group: o = r*16 + og, r = 0..7
    const int pg = t >> 4;        // point group: points pg*4 .. pg*4+3
    ull bias2[4], bias3[4];
#pragma unroll
    for (int j = 0; j < 4; ++j) {
        bias2[j] = *(const ull*)(b2s + og * 8 + 2 * j);
        bias3[j] = *(const ull*)(b3s + og * 8 + 2 * j);
    }
    const int p1  = t & 127;          // layer1: this thread's point
    const int ob1 = (t >> 7) * 16;    // layer1: output base (16 outputs)

    const float* w2ap = w2a + og * 4;
    const float* w2bp = w2b + og * 4;
    const float* w3ap = w3a + og * 4;
    const float* w3bp = w3b + og * 4;
    const float* h1p  = h1 + pg * 4;
    const float* h2p  = h2 + pg * 4;

    const int nvalid = gNvalid;
    const int nch    = (nvalid + CHUNK - 1) >> 7;

    for (int c = blockIdx.x; c < nch; c += gridDim.x) {
        const int gp = c * CHUNK;

        // -- stage sorted points + output-base offsets ----------------------
        if (t < CHUNK) {
            int idx = gp + t;
            int cell = -1;
            float4 p = make_float4(0.f, 0.f, 0.f, 0.f);
            if (idx < nvalid) {
                int pi = gSortedIdx[idx];
                p = ptsg[pi];
                int sc = gSortedCell[idx];           // b*HWSZ + pix
                cell = (sc >> 14) * BSTRIDE + (sc & (HWSZ - 1));
            }
            ptsS[t]  = p;
            cellS[t] = cell;
        }
        __syncthreads();

        // -- layer 1: 4 -> 64 ------------------------------------------------
        {
            float4 pv = ptsS[p1];
#pragma unroll
            for (int r = 0; r < 16; ++r) {
                int o = ob1 + r;
                float4 w = *(const float4*)(w1s + o * 4);
                float s = b1s[o] + pv.x * w.x + pv.y * w.y
                                 + pv.z * w.z + pv.w * w.w;
                h1[o * H1STR + p1] = fmaxf(s, 0.f);
            }
        }
        __syncthreads();

        // -- layer 2: 64 -> 128 (tile 4p x 8o, f32x2 over output pairs) -----
        ull acc[16];
#pragma unroll
        for (int p = 0; p < 4; ++p)
#pragma unroll
            for (int j = 0; j < 4; ++j) acc[p * 4 + j] = bias2[j];

#pragma unroll 8
        for (int k = 0; k < 64; ++k) {
            ulonglong2 wa = *(const ulonglong2*)(w2ap + k * 64);
            ulonglong2 wb = *(const ulonglong2*)(w2bp + k * 64);
            float4 h = *(const float4*)(h1p + k * H1STR);
            ull hx = pk2(h.x, h.x), hy = pk2(h.y, h.y);
            ull hz = pk2(h.z, h.z), hw = pk2(h.w, h.w);
            fma2(acc[0],  hx, wa.x); fma2(acc[1],  hx, wa.y);
            fma2(acc[2],  hx, wb.x); fma2(acc[3],  hx, wb.y);
            fma2(acc[4],  hy, wa.x); fma2(acc[5],  hy, wa.y);
            fma2(acc[6],  hy, wb.x); fma2(acc[7],  hy, wb.y);
            fma2(acc[8],  hz, wa.x); fma2(acc[9],  hz, wa.y);
            fma2(acc[10], hz, wb.x); fma2(acc[11], hz, wb.y);
            fma2(acc[12], hw, wa.x); fma2(acc[13], hw, wa.y);
            fma2(acc[14], hw, wb.x); fma2(acc[15], hw, wb.y);
        }
        // epilogue: ReLU + store h2 rows [o = r*16+og]
        {
            float vals[4][8];
#pragma unroll
            for (int p = 0; p < 4; ++p)
#pragma unroll
                for (int j = 0; j < 4; ++j) {
                    float2 v = up2(acc[p * 4 + j]);
                    vals[p][2 * j]     = fmaxf(v.x, 0.f);
                    vals[p][2 * j + 1] = fmaxf(v.y, 0.f);
                }
#pragma unroll
            for (int r = 0; r < 8; ++r) {
                float4 v = make_float4(vals[0][r], vals[1][r],
                                       vals[2][r], vals[3][r]);
                *(float4*)(h2 + (r * 16 + og) * H2STR + pg * 4) = v;
            }
        }
        __syncthreads();

        // -- layer 3: 128 -> 128 --------------------------------------------
#pragma unroll
        for (int p = 0; p < 4; ++p)
#pragma unroll
            for (int j = 0; j < 4; ++j) acc[p * 4 + j] = bias3[j];

#pragma unroll 8
        for (int k = 0; k < 128; ++k) {
            ulonglong2 wa = *(const ulonglong2*)(w3ap + k * 64);
            ulonglong2 wb = *(const ulonglong2*)(w3bp + k * 64);
            float4 h = *(const float4*)(h2p + k * H2STR);
            ull hx = pk2(h.x, h.x), hy = pk2(h.y, h.y);
            ull hz = pk2(h.z, h.z), hw = pk2(h.w, h.w);
            fma2(acc[0],  hx, wa.x); fma2(acc[1],  hx, wa.y);
            fma2(acc[2],  hx, wb.x); fma2(acc[3],  hx, wb.y);
            fma2(acc[4],  hy, wa.x); fma2(acc[5],  hy, wa.y);
            fma2(acc[6],  hy, wb.x); fma2(acc[7],  hy, wb.y);
            fma2(acc[8],  hz, wa.x); fma2(acc[9],  hz, wa.y);
            fma2(acc[10], hz, wb.x); fma2(acc[11], hz, wb.y);
            fma2(acc[12], hw, wa.x); fma2(acc[13], hw, wa.y);
            fma2(acc[14], hw, wb.x); fma2(acc[15], hw, wb.y);
        }

        // -- run-merged scatter-max (cells sorted => runs are adjacent) -----
        {
            float vals[4][8];
            int cells[4];
#pragma unroll
            for (int p = 0; p < 4; ++p) cells[p] = cellS[pg * 4 + p];
#pragma unroll
            for (int p = 0; p < 4; ++p)
#pragma unroll
                for (int j = 0; j < 4; ++j) {
                    float2 v = up2(acc[p * 4 + j]);
                    vals[p][2 * j]     = fmaxf(v.x, 0.f);
                    vals[p][2 * j + 1] = fmaxf(v.y, 0.f);
                }

            int cur = cells[0];
            float m[8];
#pragma unroll
            for (int j = 0; j < 8; ++j) m[j] = vals[0][j];

#pragma unroll
            for (int p = 1; p < 4; ++p) {
                if (cells[p] == cur) {
#pragma unroll
                    for (int j = 0; j < 8; ++j)
                        m[j] = fmaxf(m[j], vals[p][j]);
                } else {
                    if (cur >= 0) {
                        float* ob = out + cur + og * HWSZ;
#pragma unroll
                        for (int j = 0; j < 8; ++j)
                            atomicMax((int*)(ob + j * 16 * HWSZ),
                                      __float_as_int(m[j]));
                    }
                    cur = cells[p];
#pragma unroll
                    for (int j = 0; j < 8; ++j) m[j] = vals[p][j];
                }
            }
            if (cur >= 0) {
                float* ob = out + cur + og * HWSZ;
#pragma unroll
                for (int j = 0; j < 8; ++j)
                    atomicMax((int*)(ob + j * 16 * HWSZ),
                              __float_as_int(m[j]));
            }
        }
        __syncthreads();   // protect pts/cell/h1/h2 before next chunk
    }
}

// ---------------------------------------------------------------------------
extern "C" void kernel_launch(void* const* d_in, const int* in_sizes, int n_in,
                              void* d_out, int out_size)
{
    (void)in_sizes; (void)n_in;
    const float* points = (const float*)d_in[0];

    // Zero output BEV (post-ReLU feats >= 0; empty cells must be 0).
    cudaMemsetAsync(d_out, 0, (size_t)out_size * sizeof(float), 0);

    // Zero histogram for the sorting pre-pass.
    void* hist = nullptr;
    cudaGetSymbolAddress(&hist, gHist);
    cudaMemsetAsync(hist, 0, 65536 * sizeof(int), 0);

    fuse_kernel<<<32, 256>>>(
        (const float*)d_in[1],  (const float*)d_in[2],  (const float*)d_in[3],
        (const float*)d_in[4],  (const float*)d_in[5],  (const float*)d_in[6],
        (const float*)d_in[7],  (const float*)d_in[8],  (const float*)d_in[9],
        (const float*)d_in[10], (const float*)d_in[11], (const float*)d_in[12],
        (const float*)d_in[13], (const float*)d_in[14], (const float*)d_in[15],
        (const float*)d_in[16], (const float*)d_in[17], (const float*)d_in[18]);

    bin_kernel<<<(NALL + 255) / 256, 256>>>((const float4*)points);
    scan_kernel<<<1, 256>>>();
    sort_kernel<<<(NALL + 255) / 256, 256>>>();

    int dev = 0;
    cudaGetDevice(&dev);
    int nsm = 0;
    cudaDeviceGetAttribute(&nsm, cudaDevAttrMultiProcessorCount, dev);
    if (nsm <= 0) nsm = 148;

    cudaFuncSetAttribute(mlp_scatter_kernel,
                         cudaFuncAttributeMaxDynamicSharedMemorySize,
                         SMEM_BYTES);
    mlp_scatter_kernel<<<nsm, 512, SMEM_BYTES>>>((const float4*)points,
                                                 (float*)d_out);
}

// round 16
// speedup vs baseline: 1.7012x; 1.5360x over previous
#include <cuda_runtime.h>
#include <cuda_bf16.h>
#include <cstdint>

// ---------------------------------------------------------------------------
// SpatialLiDAREncoder round 16: HMMA (mma.sync bf16, 3-split) for layers 2/3.
// tcgen05 is unreachable (harness builds baseline compute_103 PTX), but
// mma.sync/ldmatrix are baseline PTX -> tensor pipe via HMMA.
//
//  - Pre-pass: counting sort by BEV cell; invalid points dropped.
//  - Main kernel: 512 thr (16 warps), 1 block/SM persistent, chunk = 128 pts.
//      layer1 (4->64) CUDA cores -> A1 tile bf16 hi/lo (stride 144B)
//      layer2: warp (mp,nc) computes D2[16m x 64n]; K=64; 3-split mma
//      epilogue: bias(C-init)+ReLU -> A2 tile bf16 hi/lo (stride 272B)
//      layer3: D3[16m x 64n]; K=128; 3-split mma
//      scatter: shfl segmented suffix-max over sorted rows, heads atomicMax.
//  - Strides 144/272 bytes (9,17 x 16B) make every ldmatrix phase hit 8
//    distinct 16B bank columns: conflict-free.
// ---------------------------------------------------------------------------

#define NPT      120000
#define NALL     480000
#define HWSZ     16384
#define BSTRIDE  (128 * HWSZ)
#define CHUNK    128
#define EPSF     1e-5f

// ---------------------------------------------------------------------------
// Device globals (no allocation).
__device__ float gW1f[256];        // [o][i], BN-fused
__device__ float gB1f[64];
__device__ float gW2f[128 * 64];   // [o][k]
__device__ float gB2f[128];
__device__ float gW3f[128 * 128];  // [o][k]
__device__ float gB3f[128];

__device__ int    gHist[65536];
__device__ int    gOff[65536];
__device__ int    gNvalid;
__device__ int    gCellArr[NALL];
__device__ float4 gSortedPts[NALL];
__device__ int    gSortedCell[NALL];

// ---------------------------------------------------------------------------
__global__ void fuse_kernel(
    const float* __restrict__ W1, const float* __restrict__ b1,
    const float* __restrict__ g1, const float* __restrict__ be1,
    const float* __restrict__ m1, const float* __restrict__ v1,
    const float* __restrict__ W2, const float* __restrict__ b2,
    const float* __restrict__ g2, const float* __restrict__ be2,
    const float* __restrict__ m2, const float* __restrict__ v2,
    const float* __restrict__ W3, const float* __restrict__ b3,
    const float* __restrict__ g3, const float* __restrict__ be3,
    const float* __restrict__ m3, const float* __restrict__ v3)
{
    int tid = blockIdx.x * blockDim.x + threadIdx.x;
    int nt  = gridDim.x * blockDim.x;

    for (int i = tid; i < 256; i += nt) {
        int o = i >> 2;
        gW1f[i] = W1[i] * (g1[o] * rsqrtf(v1[o] + EPSF));
    }
    for (int o = tid; o < 64; o += nt) {
        float s = g1[o] * rsqrtf(v1[o] + EPSF);
        gB1f[o] = (b1[o] - m1[o]) * s + be1[o];
    }
    for (int i = tid; i < 128 * 64; i += nt) {
        int o = i >> 6;
        gW2f[i] = W2[i] * (g2[o] * rsqrtf(v2[o] + EPSF));
    }
    for (int i = tid; i < 128 * 128; i += nt) {
        int o = i >> 7;
        gW3f[i] = W3[i] * (g3[o] * rsqrtf(v3[o] + EPSF));
    }
    for (int o = tid; o < 128; o += nt) {
        float s2 = g2[o] * rsqrtf(v2[o] + EPSF);
        gB2f[o] = (b2[o] - m2[o]) * s2 + be2[o];
        float s3 = g3[o] * rsqrtf(v3[o] + EPSF);
        gB3f[o] = (b3[o] - m3[o]) * s3 + be3[o];
    }
}

// ---------------------------------------------------------------------------
// Sorting pre-pass.
__global__ void bin_kernel(const float4* __restrict__ pts)
{
    int i = blockIdx.x * blockDim.x + threadIdx.x;
    if (i >= NALL) return;
    float4 p = pts[i];
    float xn = (p.x + 50.f) * 0.01f;
    float yn = (p.y + 50.f) * 0.01f;
    bool valid = (xn >= 0.f) && (xn <= 1.f) && (yn >= 0.f) && (yn <= 1.f);
    int gx = min(max((int)(xn * 127.f), 0), 127);
    int gy = min(max((int)(yn * 127.f), 0), 127);
    int b  = i / NPT;
    int sc = valid ? (b * HWSZ + gy * 128 + gx) : -1;
    gCellArr[i] = sc;
    if (sc >= 0) atomicAdd(&gHist[sc], 1);
}

__global__ void scan_kernel()   // single block, 256 threads
{
    __shared__ int ssum[256];
    int t = threadIdx.x;
    int base = t * 256;
    int s = 0;
#pragma unroll 8
    for (int i = 0; i < 256; ++i) s += gHist[base + i];
    ssum[t] = s;
    __syncthreads();
    for (int d = 1; d < 256; d <<= 1) {
        int v = (t >= d) ? ssum[t - d] : 0;
        __syncthreads();
        ssum[t] += v;
        __syncthreads();
    }
    int run = (t == 0) ? 0 : ssum[t - 1];
#pragma unroll 8
    for (int i = 0; i < 256; ++i) {
        int h = gHist[base + i];
        gOff[base + i] = run;
        run += h;
    }
    if (t == 255) gNvalid = run;
}

__global__ void sort_kernel(const float4* __restrict__ pts)
{
    int i = blockIdx.x * blockDim.x + threadIdx.x;
    if (i >= NALL) return;
    int sc = gCellArr[i];
    if (sc >= 0) {
        int pos = atomicAdd(&gOff[sc], 1);
        gSortedPts[pos]  = pts[i];
        gSortedCell[pos] = sc;
    }
}

// ---------------------------------------------------------------------------
// Helpers.
__device__ __forceinline__ uint32_t smem_u32(const void* p) {
    uint32_t a;
    asm("{ .reg .u64 t; cvta.to.shared.u64 t, %1; cvt.u32.u64 %0, t; }"
        : "=r"(a) : "l"(p));
    return a;
}
__device__ __forceinline__ unsigned short f2bf(float v) {
    unsigned short u;
    asm("cvt.rn.bf16.f32 %0, %1;" : "=h"(u) : "f"(v));
    return u;
}
__device__ __forceinline__ float bf2f(unsigned short u) {
    float f;
    asm("cvt.f32.bf16 %0, %1;" : "=f"(f) : "h"(u));
    return f;
}
__device__ __forceinline__ void ldsm4(uint32_t* r, uint32_t addr) {
    asm volatile("ldmatrix.sync.aligned.m8n8.x4.shared.b16 {%0,%1,%2,%3}, [%4];"
                 : "=r"(r[0]), "=r"(r[1]), "=r"(r[2]), "=r"(r[3]) : "r"(addr));
}
__device__ __forceinline__ void mma16816(float* d, const uint32_t* a,
                                         uint32_t b0, uint32_t b1) {
    asm volatile(
        "mma.sync.aligned.m16n8k16.row.col.f32.bf16.bf16.f32 "
        "{%0,%1,%2,%3}, {%4,%5,%6,%7}, {%8,%9}, {%0,%1,%2,%3};"
        : "+f"(d[0]), "+f"(d[1]), "+f"(d[2]), "+f"(d[3])
        : "r"(a[0]), "r"(a[1]), "r"(a[2]), "r"(a[3]), "r"(b0), "r"(b1));
}

// Pack two floats to a bf16x2 word (lo = first).
__device__ __forceinline__ uint32_t pkbf(unsigned short l, unsigned short h) {
    return (uint32_t)l | ((uint32_t)h << 16);
}

// ---------------------------------------------------------------------------
// Shared memory layout (byte offsets). Strides: 144B (K=64), 272B (K=128).
#define STR64   144
#define STR128  272
#define SM_W2HI 0
#define SM_W2LO 18432
#define SM_W3HI 36864
#define SM_W3LO 71680
#define SM_A1HI 106496
#define SM_A1LO 124928
#define SM_A2HI 143360
#define SM_A2LO 178176
#define SM_W1   212992
#define SM_B1S  214016
#define SM_B2S  214272
#define SM_B3S  214784
#define SM_PTS  215296
#define SM_CEL  217344
#define SMEM_BYTES (217344 + 512)   // 217856

__global__ void __launch_bounds__(512, 1)
mlp_mma_kernel(float* __restrict__ out)
{
    extern __shared__ char smem[];
    const uint32_t sb = smem_u32(smem);
    const int t = threadIdx.x, wid = t >> 5, lane = t & 31;

    // -- stage fused weights as bf16 hi/lo ----------------------------------
    for (int i = t; i < 128 * 64; i += 512) {
        int o = i >> 6, k = i & 63;
        float v = gW2f[i];
        unsigned short h = f2bf(v);
        unsigned short l = f2bf(v - bf2f(h));
        *(unsigned short*)(smem + SM_W2HI + o * STR64 + k * 2) = h;
        *(unsigned short*)(smem + SM_W2LO + o * STR64 + k * 2) = l;
    }
    for (int i = t; i < 128 * 128; i += 512) {
        int o = i >> 7, k = i & 127;
        float v = gW3f[i];
        unsigned short h = f2bf(v);
        unsigned short l = f2bf(v - bf2f(h));
        *(unsigned short*)(smem + SM_W3HI + o * STR128 + k * 2) = h;
        *(unsigned short*)(smem + SM_W3LO + o * STR128 + k * 2) = l;
    }
    float* w1s = (float*)(smem + SM_W1);
    float* b1s = (float*)(smem + SM_B1S);
    float* b2s = (float*)(smem + SM_B2S);
    float* b3s = (float*)(smem + SM_B3S);
    if (t < 256) w1s[t] = gW1f[t];
    if (t < 64)  b1s[t] = gB1f[t];
    if (t < 128) { b2s[t] = gB2f[t]; b3s[t] = gB3f[t]; }

    float4* ptsS  = (float4*)(smem + SM_PTS);
    int*    cellS = (int*)(smem + SM_CEL);

    // warp tiling: mp = point tile (16 rows), nc = feature half (64 cols)
    const int mp = wid & 7;
    const int nc = wid >> 3;
    const int mrow = mp * 16;
    const int nbase = nc * 64;

    // ldmatrix address components (x4: m0 r0-7/k0-7, m1 r8-15/k0-7,
    // m2 r0-7/k8-15, m3 r8-15/k8-15)
    const int lrow = (lane & 7) + ((lane >> 3) & 1) * 8;
    const int lcol = (lane >> 4) * 16;

    const int qr = lane >> 2;           // 0..7 (row within 8)
    const int qc = (lane & 3) * 2;      // col pair base

    const int p1  = t & 127;            // layer1: point
    const int ob1 = (t >> 7) * 16;      // layer1: 16 feats base

    // bias C-init values for this thread's columns
    float cb2[8][2], cb3[8][2];
#pragma unroll
    for (int nf = 0; nf < 8; ++nf) {
        int col = nbase + nf * 8 + qc;
        cb2[nf][0] = gB2f[col]; cb2[nf][1] = gB2f[col + 1];
        cb3[nf][0] = gB3f[col]; cb3[nf][1] = gB3f[col + 1];
    }
    __syncthreads();

    const int nvalid = gNvalid;
    const int nch = (nvalid + CHUNK - 1) >> 7;

    for (int c = blockIdx.x; c < nch; c += gridDim.x) {
        const int gp = c * CHUNK;
        __syncthreads();   // protect pts/cell/A tiles from previous iteration

        // -- stage sorted points + out-base offsets -------------------------
        if (t < CHUNK) {
            int idx = gp + t;
            float4 p = make_float4(0.f, 0.f, 0.f, 0.f);
            int cell = -1;
            if (idx < nvalid) {
                p = gSortedPts[idx];
                int sc = gSortedCell[idx];
                cell = (sc >> 14) * BSTRIDE + (sc & (HWSZ - 1));
            }
            ptsS[t]  = p;
            cellS[t] = cell;
        }
        __syncthreads();

        // -- layer 1 (CUDA cores): A1 tile bf16 hi/lo -----------------------
        {
            float4 pv = ptsS[p1];
            uint32_t hi[8], lo[8];
#pragma unroll
            for (int r = 0; r < 16; ++r) {
                int o = ob1 + r;
                float4 w = *(const float4*)(w1s + o * 4);
                float s = b1s[o] + pv.x * w.x + pv.y * w.y
                                 + pv.z * w.z + pv.w * w.w;
                s = fmaxf(s, 0.f);
                unsigned short h = f2bf(s);
                unsigned short l = f2bf(s - bf2f(h));
                if (r & 1) { hi[r >> 1] |= (uint32_t)h << 16;
                             lo[r >> 1] |= (uint32_t)l << 16; }
                else       { hi[r >> 1] = h; lo[r >> 1] = l; }
            }
            char* dh = smem + SM_A1HI + p1 * STR64 + ob1 * 2;
            char* dl = smem + SM_A1LO + p1 * STR64 + ob1 * 2;
            *(uint4*)(dh)      = make_uint4(hi[0], hi[1], hi[2], hi[3]);
            *(uint4*)(dh + 16) = make_uint4(hi[4], hi[5], hi[6], hi[7]);
            *(uint4*)(dl)      = make_uint4(lo[0], lo[1], lo[2], lo[3]);
            *(uint4*)(dl + 16) = make_uint4(lo[4], lo[5], lo[6], lo[7]);
        }
        __syncthreads();

        // -- layer 2: D2[16m x 64n] = A1 * W2^T, K=64, 3-split --------------
        float d2[8][4];
#pragma unroll
        for (int nf = 0; nf < 8; ++nf) {
            d2[nf][0] = cb2[nf][0]; d2[nf][1] = cb2[nf][1];
            d2[nf][2] = cb2[nf][0]; d2[nf][3] = cb2[nf][1];
        }
        {
            const uint32_t aHbase = sb + SM_A1HI + (mrow + lrow) * STR64 + lcol;
            const uint32_t aLbase = sb + SM_A1LO + (mrow + lrow) * STR64 + lcol;
#pragma unroll
            for (int ks = 0; ks < 4; ++ks) {
                uint32_t ah[4], al[4];
                ldsm4(ah, aHbase + ks * 32);
                ldsm4(al, aLbase + ks * 32);
#pragma unroll
                for (int nb = 0; nb < 4; ++nb) {
                    int brow = nbase + nb * 16 + lrow;
                    uint32_t bh[4], bl[4];
                    ldsm4(bh, sb + SM_W2HI + brow * STR64 + ks * 32 + lcol);
                    ldsm4(bl, sb + SM_W2LO + brow * STR64 + ks * 32 + lcol);
                    mma16816(d2[nb * 2],     ah, bh[0], bh[2]);
                    mma16816(d2[nb * 2 + 1], ah, bh[1], bh[3]);
                    mma16816(d2[nb * 2],     ah, bl[0], bl[2]);
                    mma16816(d2[nb * 2 + 1], ah, bl[1], bl[3]);
                    mma16816(d2[nb * 2],     al, bh[0], bh[2]);
                    mma16816(d2[nb * 2 + 1], al, bh[1], bh[3]);
                }
            }
        }
        // epilogue: ReLU -> A2 tile bf16 hi/lo (rows m, cols = feature)
        {
            int r0 = mrow + qr, r1 = r0 + 8;
#pragma unroll
            for (int nf = 0; nf < 8; ++nf) {
                int colb = (nbase + nf * 8 + qc) * 2;
                float v0 = fmaxf(d2[nf][0], 0.f);
                float v1 = fmaxf(d2[nf][1], 0.f);
                float v2 = fmaxf(d2[nf][2], 0.f);
                float v3 = fmaxf(d2[nf][3], 0.f);
                unsigned short h0 = f2bf(v0), h1 = f2bf(v1);
                unsigned short h2 = f2bf(v2), h3 = f2bf(v3);
                unsigned short l0 = f2bf(v0 - bf2f(h0));
                unsigned short l1 = f2bf(v1 - bf2f(h1));
                unsigned short l2 = f2bf(v2 - bf2f(h2));
                unsigned short l3 = f2bf(v3 - bf2f(h3));
                *(uint32_t*)(smem + SM_A2HI + r0 * STR128 + colb) = pkbf(h0, h1);
                *(uint32_t*)(smem + SM_A2HI + r1 * STR128 + colb) = pkbf(h2, h3);
                *(uint32_t*)(smem + SM_A2LO + r0 * STR128 + colb) = pkbf(l0, l1);
                *(uint32_t*)(smem + SM_A2LO + r1 * STR128 + colb) = pkbf(l2, l3);
            }
        }
        __syncthreads();

        // -- layer 3: D3[16m x 64n] = A2 * W3^T, K=128, 3-split -------------
        float d3[8][4];
#pragma unroll
        for (int nf = 0; nf < 8; ++nf) {
            d3[nf][0] = cb3[nf][0]; d3[nf][1] = cb3[nf][1];
            d3[nf][2] = cb3[nf][0]; d3[nf][3] = cb3[nf][1];
        }
        {
            const uint32_t aHbase = sb + SM_A2HI + (mrow + lrow) * STR128 + lcol;
            const uint32_t aLbase = sb + SM_A2LO + (mrow + lrow) * STR128 + lcol;
#pragma unroll
            for (int ks = 0; ks < 8; ++ks) {
                uint32_t ah[4], al[4];
                ldsm4(ah, aHbase + ks * 32);
                ldsm4(al, aLbase + ks * 32);
#pragma unroll
                for (int nb = 0; nb < 4; ++nb) {
                    int brow = nbase + nb * 16 + lrow;
                    uint32_t bh[4], bl[4];
                    ldsm4(bh, sb + SM_W3HI + brow * STR128 + ks * 32 + lcol);
                    ldsm4(bl, sb + SM_W3LO + brow * STR128 + ks * 32 + lcol);
                    mma16816(d3[nb * 2],     ah, bh[0], bh[2]);
                    mma16816(d3[nb * 2 + 1], ah, bh[1], bh[3]);
                    mma16816(d3[nb * 2],     ah, bl[0], bl[2]);
                    mma16816(d3[nb * 2 + 1], ah, bl[1], bl[3]);
                    mma16816(d3[nb * 2],     al, bh[0], bh[2]);
                    mma16816(d3[nb * 2 + 1], al, bh[1], bh[3]);
                }
            }
        }

        // -- scatter: segmented suffix-max over sorted rows, heads only -----
        {
            int r0 = mrow + qr, r1 = r0 + 8;
            int c0 = cellS[r0], c1 = cellS[r1];
            float v0[16], v1[16];
#pragma unroll
            for (int nf = 0; nf < 8; ++nf) {
                v0[nf * 2]     = fmaxf(d3[nf][0], 0.f);
                v0[nf * 2 + 1] = fmaxf(d3[nf][1], 0.f);
                v1[nf * 2]     = fmaxf(d3[nf][2], 0.f);
                v1[nf * 2 + 1] = fmaxf(d3[nf][3], 0.f);
            }
            // rows ascend with lane/4 (stride-4 lane groups share columns)
#pragma unroll
            for (int d = 4; d <= 16; d <<= 1) {
                int oc0 = __shfl_down_sync(0xffffffffu, c0, d);
                int oc1 = __shfl_down_sync(0xffffffffu, c1, d);
                bool m0 = (oc0 == c0), m1 = (oc1 == c1);
#pragma unroll
                for (int j = 0; j < 16; ++j) {
                    float o0 = __shfl_down_sync(0xffffffffu, v0[j], d);
                    float o1 = __shfl_down_sync(0xffffffffu, v1[j], d);
                    if (m0) v0[j] = fmaxf(v0[j], o0);
                    if (m1) v1[j] = fmaxf(v1[j], o1);
                }
            }
            int pc0 = __shfl_up_sync(0xffffffffu, c0, 4);
            int pc1 = __shfl_up_sync(0xffffffffu, c1, 4);
            bool head0 = (qr == 0) || (pc0 != c0);
            bool head1 = (qr == 0) || (pc1 != c1);
            if (head0 && c0 >= 0) {
                float* ob = out + c0;
#pragma unroll
                for (int j = 0; j < 16; ++j) {
                    int col = nbase + (j >> 1) * 8 + qc + (j & 1);
                    atomicMax((int*)(ob + col * HWSZ), __float_as_int(v0[j]));
                }
            }
            if (head1 && c1 >= 0) {
                float* ob = out + c1;
#pragma unroll
                for (int j = 0; j < 16; ++j) {
                    int col = nbase + (j >> 1) * 8 + qc + (j & 1);
                    atomicMax((int*)(ob + col * HWSZ), __float_as_int(v1[j]));
                }
            }
        }
    }
}

// ---------------------------------------------------------------------------
extern "C" void kernel_launch(void* const* d_in, const int* in_sizes, int n_in,
                              void* d_out, int out_size)
{
    (void)in_sizes; (void)n_in;
    const float* points = (const float*)d_in[0];

    cudaMemsetAsync(d_out, 0, (size_t)out_size * sizeof(float), 0);

    void* hist = nullptr;
    cudaGetSymbolAddress(&hist, gHist);
    cudaMemsetAsync(hist, 0, 65536 * sizeof(int), 0);

    fuse_kernel<<<32, 256>>>(
        (const float*)d_in[1],  (const float*)d_in[2],  (const float*)d_in[3],
        (const float*)d_in[4],  (const float*)d_in[5],  (const float*)d_in[6],
        (const float*)d_in[7],  (const float*)d_in[8],  (const float*)d_in[9],
        (const float*)d_in[10], (const float*)d_in[11], (const float*)d_in[12],
        (const float*)d_in[13], (const float*)d_in[14], (const float*)d_in[15],
        (const float*)d_in[16], (const float*)d_in[17], (const float*)d_in[18]);

    bin_kernel<<<(NALL + 255) / 256, 256>>>((const float4*)points);
    scan_kernel<<<1, 256>>>();
    sort_kernel<<<(NALL + 255) / 256, 256>>>((const float4*)points);

    int dev = 0;
    cudaGetDevice(&dev);
    int nsm = 0;
    cudaDeviceGetAttribute(&nsm, cudaDevAttrMultiProcessorCount, dev);
    if (nsm <= 0) nsm = 148;

    cudaFuncSetAttribute(mlp_mma_kernel,
                         cudaFuncAttributeMaxDynamicSharedMemorySize,
                         SMEM_BYTES);
    mlp_mma_kernel<<<nsm, 512, SMEM_BYTES>>>((float*)d_out);
}